// round 1
// baseline (speedup 1.0000x reference)
#include <cuda_runtime.h>
#include <cstdint>

#define BATCH 2
#define CIN   64
#define NTOK  9216          // 96*96
#define C1    8

// ---------------- scratch (device globals; allocation-free) ----------------
__device__ float g_q[BATCH * NTOK * C1];    // [b][i][8]
__device__ float g_k[BATCH * NTOK * C1];    // [b][j][8]
__device__ float g_v[BATCH * NTOK * CIN];   // [b][j][64]
__device__ float g_z[BATCH * NTOK];         // Z_j = sum_i exp(q_i . k_j)

// packed f32x2 FMA: d = a*b + d  (2 fp32 lanes per instruction)
__device__ __forceinline__ void ffma2(unsigned long long& d,
                                      unsigned long long a,
                                      unsigned long long b) {
    asm volatile("fma.rn.f32x2 %0, %1, %2, %0;" : "+l"(d) : "l"(a), "l"(b));
}
__device__ __forceinline__ unsigned long long pack2(float lo, float hi) {
    unsigned long long r;
    asm("mov.b64 %0, {%1, %2};" : "=l"(r) : "f"(lo), "f"(hi));
    return r;
}
__device__ __forceinline__ void unpack2(float& lo, float& hi, unsigned long long v) {
    asm("mov.b64 {%0, %1}, %2;" : "=f"(lo), "=f"(hi) : "l"(v));
}

// ---------------- K1: fused q/k/v 1x1 convs ----------------
// grid = BATCH*NTOK/128 blocks of 128 threads; thread -> one token i.
__global__ void qkv_kernel(const float* __restrict__ X, const float* __restrict__ Y,
                           const float* __restrict__ Wq, const float* __restrict__ bq,
                           const float* __restrict__ Wk, const float* __restrict__ bk,
                           const float* __restrict__ Wv, const float* __restrict__ bv) {
    __shared__ float sWq[C1 * CIN], sWk[C1 * CIN], sWv[CIN * CIN];
    __shared__ float sbq[C1], sbk[C1], sbv[CIN];
    int tid = threadIdx.x;
    for (int idx = tid; idx < C1 * CIN; idx += 128) { sWq[idx] = Wq[idx]; sWk[idx] = Wk[idx]; }
    for (int idx = tid; idx < CIN * CIN; idx += 128) sWv[idx] = Wv[idx];
    if (tid < C1)  { sbq[tid] = bq[tid]; sbk[tid] = bk[tid]; }
    if (tid < CIN) sbv[tid] = bv[tid];
    __syncthreads();

    int gi = blockIdx.x * 128 + tid;        // 0 .. B*N-1
    int b = gi / NTOK, i = gi - b * NTOK;
    const float* Xp = X + (size_t)b * CIN * NTOK + i;
    const float* Yp = Y + (size_t)b * CIN * NTOK + i;

    float accq[C1], acck[C1], accv[CIN];
#pragma unroll
    for (int o = 0; o < C1; o++) { accq[o] = 0.f; acck[o] = 0.f; }
#pragma unroll
    for (int o = 0; o < CIN; o++) accv[o] = 0.f;

#pragma unroll 1
    for (int c = 0; c < CIN; c++) {
        float xv = Xp[(size_t)c * NTOK];
        float yv = Yp[(size_t)c * NTOK];
#pragma unroll
        for (int o = 0; o < C1; o++) {
            accq[o] += sWq[o * CIN + c] * xv;
            acck[o] += sWk[o * CIN + c] * xv;
        }
#pragma unroll
        for (int o = 0; o < CIN; o++) accv[o] += sWv[o * CIN + c] * yv;
    }

    float4* qp = (float4*)(g_q + (size_t)gi * C1);
    float4* kp = (float4*)(g_k + (size_t)gi * C1);
    float4* vp = (float4*)(g_v + (size_t)gi * CIN);
    float4 t;
    t.x = accq[0] + sbq[0]; t.y = accq[1] + sbq[1]; t.z = accq[2] + sbq[2]; t.w = accq[3] + sbq[3];
    qp[0] = t;
    t.x = accq[4] + sbq[4]; t.y = accq[5] + sbq[5]; t.z = accq[6] + sbq[6]; t.w = accq[7] + sbq[7];
    qp[1] = t;
    t.x = acck[0] + sbk[0]; t.y = acck[1] + sbk[1]; t.z = acck[2] + sbk[2]; t.w = acck[3] + sbk[3];
    kp[0] = t;
    t.x = acck[4] + sbk[4]; t.y = acck[5] + sbk[5]; t.z = acck[6] + sbk[6]; t.w = acck[7] + sbk[7];
    kp[1] = t;
#pragma unroll
    for (int o4 = 0; o4 < CIN / 4; o4++) {
        t.x = accv[o4 * 4 + 0] + sbv[o4 * 4 + 0];
        t.y = accv[o4 * 4 + 1] + sbv[o4 * 4 + 1];
        t.z = accv[o4 * 4 + 2] + sbv[o4 * 4 + 2];
        t.w = accv[o4 * 4 + 3] + sbv[o4 * 4 + 3];
        vp[o4] = t;
    }
}

// ---------------- K2: column softmax denominators Z_j ----------------
// grid = BATCH * (NTOK/64) blocks of 256 threads.
// Thread layout: jl = tid&63 (j within the 64-j tile), rep = tid>>6 (splits each
// staged i-tile 4 ways). All 256 threads sweep the full i range together.
__global__ void zsum_kernel() {
    __shared__ float4 sq[512];            // 256 i's * 8 floats
    __shared__ float  zred[4][64];
    int tid = threadIdx.x;
    int nb = NTOK / 64;
    int b  = blockIdx.x / nb;
    int j0 = (blockIdx.x - b * nb) * 64;
    int jl  = tid & 63;
    int rep = tid >> 6;

    const float4* kp = (const float4*)(g_k + ((size_t)b * NTOK + j0 + jl) * C1);
    float4 k0 = kp[0], k1 = kp[1];
    const float4* qbase = (const float4*)(g_q + (size_t)b * NTOK * C1);

    float zacc = 0.f;
    for (int it = 0; it < NTOK; it += 256) {
        sq[tid]       = qbase[it * 2 + tid];
        sq[tid + 256] = qbase[it * 2 + tid + 256];
        __syncthreads();
#pragma unroll 4
        for (int ii = rep; ii < 256; ii += 4) {
            float4 qa = sq[ii * 2], qb = sq[ii * 2 + 1];
            float s = qa.x * k0.x + qa.y * k0.y + qa.z * k0.z + qa.w * k0.w
                    + qb.x * k1.x + qb.y * k1.y + qb.z * k1.z + qb.w * k1.w;
            zacc += __expf(s);
        }
        __syncthreads();
    }
    zred[rep][jl] = zacc;
    __syncthreads();
    if (tid < 64)
        g_z[(size_t)b * NTOK + j0 + tid] =
            zred[0][tid] + zred[1][tid] + zred[2][tid] + zred[3][tid];
}

// ---------------- K3: x = A * V fused with out = Y + x ----------------
// grid = BATCH * (NTOK/64) blocks of 256 threads, 64-i x 128-j tiles.
// Dynamic smem partitions:
#define SV_F4   (128 * 16)        // V tile 128 x 64 floats
#define SW_ELEM (64 * 129)        // W tile, padded stride 129
#define SK_F4   (128 * 2)         // K tile 128 x 8 floats
#define SQ_F4   (64 * 2)          // Q tile 64 x 8 floats
#define K3_SMEM_BYTES (SV_F4 * 16 + SW_ELEM * 4 + SK_F4 * 16 + SQ_F4 * 16 + 128 * 4)

__global__ void attn_kernel(const float* __restrict__ Y, float* __restrict__ out) {
    extern __shared__ char smem[];
    float4* sV4 = (float4*)smem;                              // 32768 B
    float*  sW  = (float*)(smem + SV_F4 * 16);                // 33024 B
    float4* sK4 = (float4*)(smem + SV_F4 * 16 + SW_ELEM * 4); // 4096 B
    float4* sQ4 = (float4*)((char*)sK4 + SK_F4 * 16);         // 2048 B
    float*  srz = (float*)((char*)sQ4 + SQ_F4 * 16);          // 512 B
    unsigned long long* sV64 = (unsigned long long*)sV4;

    int tid = threadIdx.x;
    int nb = NTOK / 64;
    int b  = blockIdx.x / nb;
    int i0 = (blockIdx.x - b * nb) * 64;

    // stage Q for this block's 64 rows (once)
    if (tid < 128) sQ4[tid] = ((const float4*)(g_q + ((size_t)b * NTOK + i0) * C1))[tid];

    // phase-1 thread roles
    int jj1 = tid & 127;
    int ih  = tid >> 7;                 // 0..1 -> ii range
    // phase-2 thread roles
    int cq2 = tid & 7;                  // 8 floats of c, starting at cq2*8
    int ig  = tid >> 3;                 // 0..31 -> two i rows ig*2, ig*2+1

    unsigned long long acc[2][4];
#pragma unroll
    for (int r = 0; r < 2; r++)
#pragma unroll
        for (int p = 0; p < 4; p++) acc[r][p] = 0ULL;

    const float4* gv4 = (const float4*)(g_v + (size_t)b * NTOK * CIN);
    const float4* gk4 = (const float4*)(g_k + (size_t)b * NTOK * C1);
    const float*  gz  = g_z + (size_t)b * NTOK;

    for (int jt = 0; jt < NTOK; jt += 128) {
        __syncthreads();   // previous phase-2 done before restaging
        // stage V tile: 2048 float4, coalesced
#pragma unroll
        for (int t = 0; t < 8; t++)
            sV4[tid + t * 256] = gv4[(size_t)jt * 16 + tid + t * 256];
        // stage K tile: 256 float4
        sK4[tid] = gk4[(size_t)jt * 2 + tid];
        // stage 1/Z
        if (tid < 128) srz[tid] = 1.0f / gz[jt + tid];
        __syncthreads();

        // phase 1: W[ii][jj] = exp(q_i . k_j) / Z_j
        {
            float4 ka = sK4[jj1 * 2], kb = sK4[jj1 * 2 + 1];
            float rz = srz[jj1];
            int iiBeg = ih * 32;
#pragma unroll 4
            for (int ii = iiBeg; ii < iiBeg + 32; ii++) {
                float4 qa = sQ4[ii * 2], qb = sQ4[ii * 2 + 1];
                float s = qa.x * ka.x + qa.y * ka.y + qa.z * ka.z + qa.w * ka.w
                        + qb.x * kb.x + qb.y * kb.y + qb.z * kb.z + qb.w * kb.w;
                sW[ii * 129 + jj1] = __expf(s) * rz;
            }
        }
        __syncthreads();

        // phase 2: acc += W * V   (packed f32x2 FMAs)
#pragma unroll 4
        for (int jj = 0; jj < 128; jj++) {
            const unsigned long long* vrow = sV64 + (size_t)jj * 32 + cq2 * 4;
            ulonglong2 va = *(const ulonglong2*)(vrow);
            ulonglong2 vb = *(const ulonglong2*)(vrow + 2);
            unsigned long long w0 = pack2(sW[(ig * 2 + 0) * 129 + jj], sW[(ig * 2 + 0) * 129 + jj]);
            unsigned long long w1 = pack2(sW[(ig * 2 + 1) * 129 + jj], sW[(ig * 2 + 1) * 129 + jj]);
            ffma2(acc[0][0], w0, va.x); ffma2(acc[0][1], w0, va.y);
            ffma2(acc[0][2], w0, vb.x); ffma2(acc[0][3], w0, vb.y);
            ffma2(acc[1][0], w1, va.x); ffma2(acc[1][1], w1, va.y);
            ffma2(acc[1][2], w1, vb.x); ffma2(acc[1][3], w1, vb.y);
        }
    }

    // epilogue: out[b][c][i] = Y[b][c][i] + x[i][c]
    const float* Yb = Y + (size_t)b * CIN * NTOK;
    float* outb = out + (size_t)b * CIN * NTOK;
#pragma unroll
    for (int r = 0; r < 2; r++) {
        int i = i0 + ig * 2 + r;
#pragma unroll
        for (int p = 0; p < 4; p++) {
            float lo, hi;
            unpack2(lo, hi, acc[r][p]);
            int c0 = cq2 * 8 + p * 2;
            outb[(size_t)c0 * NTOK + i]       = Yb[(size_t)c0 * NTOK + i] + lo;
            outb[(size_t)(c0 + 1) * NTOK + i] = Yb[(size_t)(c0 + 1) * NTOK + i] + hi;
        }
    }
}

// ---------------- launch ----------------
extern "C" void kernel_launch(void* const* d_in, const int* in_sizes, int n_in,
                              void* d_out, int out_size) {
    const float* X  = (const float*)d_in[0];
    const float* Y  = (const float*)d_in[1];
    const float* Wq = (const float*)d_in[2];
    const float* bq = (const float*)d_in[3];
    const float* Wk = (const float*)d_in[4];
    const float* bk = (const float*)d_in[5];
    const float* Wv = (const float*)d_in[6];
    const float* bv = (const float*)d_in[7];
    float* out = (float*)d_out;

    cudaFuncSetAttribute(attn_kernel, cudaFuncAttributeMaxDynamicSharedMemorySize,
                         K3_SMEM_BYTES);

    qkv_kernel<<<BATCH * NTOK / 128, 128>>>(X, Y, Wq, bq, Wk, bk, Wv, bv);
    zsum_kernel<<<BATCH * (NTOK / 64), 256>>>();
    attn_kernel<<<BATCH * (NTOK / 64), 256, K3_SMEM_BYTES>>>(Y, out);
}

// round 3
// speedup vs baseline: 4.5246x; 4.5246x over previous
#include <cuda_runtime.h>
#include <cuda_fp16.h>
#include <cstdint>

#define BATCH 2
#define CIN   64
#define NTOK  9216
#define C1    8
#define NT128 72                  // NTOK / 128
#define NKC   144                 // NTOK / 64  (K-chunks for K4)
#define LOG2E 1.4426950408889634f
#define ESH   5.770780163555854f  // 4 * log2(e)  (exp shift C=4 in exp2 domain)

// ---------------- scratch ----------------
__device__ float  g_q [BATCH * NTOK * C1];
__device__ float  g_k [BATCH * NTOK * C1];
__device__ __half g_vt[BATCH * CIN * NTOK];           // V'^T fp16: [b][c][j], prescaled by 1/Z'
__device__ float  g_zp[NT128 * BATCH * NTOK];         // Z partials per i-tile
__device__ __half g_p [(size_t)BATCH * NTOK * NTOK];  // P' = exp(s - 4), fp16, [b][i][j]

// ---------------- small PTX helpers ----------------
__device__ __forceinline__ float ex2f(float x) {
    float r; asm("ex2.approx.f32 %0, %1;" : "=f"(r) : "f"(x)); return r;
}
__device__ __forceinline__ uint32_t pack_h2(float lo, float hi) {
    uint32_t r; asm("cvt.rn.f16x2.f32 %0, %1, %2;" : "=r"(r) : "f"(hi), "f"(lo)); return r;
}
__device__ __forceinline__ void cp_async16(uint32_t saddr, const void* g) {
    asm volatile("cp.async.cg.shared.global [%0], [%1], 16;\n" :: "r"(saddr), "l"(g));
}
__device__ __forceinline__ void ldsm4(uint32_t& r0, uint32_t& r1, uint32_t& r2, uint32_t& r3,
                                      uint32_t a) {
    asm volatile("ldmatrix.sync.aligned.m8n8.x4.shared.b16 {%0,%1,%2,%3}, [%4];"
                 : "=r"(r0), "=r"(r1), "=r"(r2), "=r"(r3) : "r"(a));
}
__device__ __forceinline__ void mma16816(float& d0, float& d1, float& d2, float& d3,
                                         uint32_t a0, uint32_t a1, uint32_t a2, uint32_t a3,
                                         uint32_t b0, uint32_t b1) {
    asm volatile(
        "mma.sync.aligned.m16n8k16.row.col.f32.f16.f16.f32 "
        "{%0,%1,%2,%3}, {%4,%5,%6,%7}, {%8,%9}, {%0,%1,%2,%3};"
        : "+f"(d0), "+f"(d1), "+f"(d2), "+f"(d3)
        : "r"(a0), "r"(a1), "r"(a2), "r"(a3), "r"(b0), "r"(b1));
}

// ---------------- K1: q,k 1x1 convs ----------------
__global__ void qk_kernel(const float* __restrict__ X,
                          const float* __restrict__ Wq, const float* __restrict__ bq,
                          const float* __restrict__ Wk, const float* __restrict__ bk) {
    __shared__ float sW[16 * CIN];   // [c][o]: o 0-7 = Wq rows, 8-15 = Wk rows
    int tid = threadIdx.x;
    for (int t = tid; t < 16 * CIN; t += 128) {
        int c = t >> 4, o = t & 15;
        sW[t] = (o < 8) ? Wq[o * CIN + c] : Wk[(o - 8) * CIN + c];
    }
    __syncthreads();

    int gi = blockIdx.x * 128 + tid;
    int b = gi / NTOK, i = gi - b * NTOK;
    const float* Xp = X + (size_t)b * CIN * NTOK + i;

    float acc[16];
#pragma unroll
    for (int o = 0; o < 16; o++) acc[o] = 0.f;

#pragma unroll 8
    for (int c = 0; c < CIN; c++) {
        float xv = Xp[(size_t)c * NTOK];
        const float4* w4 = (const float4*)&sW[c * 16];
        float4 w0 = w4[0], w1 = w4[1], w2 = w4[2], w3 = w4[3];
        acc[0] += w0.x * xv; acc[1] += w0.y * xv; acc[2] += w0.z * xv; acc[3] += w0.w * xv;
        acc[4] += w1.x * xv; acc[5] += w1.y * xv; acc[6] += w1.z * xv; acc[7] += w1.w * xv;
        acc[8] += w2.x * xv; acc[9] += w2.y * xv; acc[10] += w2.z * xv; acc[11] += w2.w * xv;
        acc[12] += w3.x * xv; acc[13] += w3.y * xv; acc[14] += w3.z * xv; acc[15] += w3.w * xv;
    }

    float4* qp = (float4*)(g_q + (size_t)gi * C1);
    float4* kp = (float4*)(g_k + (size_t)gi * C1);
    float4 t;
    t.x = acc[0] + bq[0]; t.y = acc[1] + bq[1]; t.z = acc[2] + bq[2]; t.w = acc[3] + bq[3];
    qp[0] = t;
    t.x = acc[4] + bq[4]; t.y = acc[5] + bq[5]; t.z = acc[6] + bq[6]; t.w = acc[7] + bq[7];
    qp[1] = t;
    t.x = acc[8] + bk[0]; t.y = acc[9] + bk[1]; t.z = acc[10] + bk[2]; t.w = acc[11] + bk[3];
    kp[0] = t;
    t.x = acc[12] + bk[4]; t.y = acc[13] + bk[5]; t.z = acc[14] + bk[6]; t.w = acc[15] + bk[7];
    kp[1] = t;
}

// ---------------- K2: P' = exp(QK^T - 4) fp16 + Z partials ----------------
// grid (NT128 j-tiles, NT128 i-tiles, BATCH), block 256: thread = 8i x 8j micro-tile
__global__ void pexp_kernel() {
    __shared__ float4 sq[256], sk[256];
    __shared__ float  szp[16 * 128];          // [ti][c][tj]
    int tid = threadIdx.x;
    int b  = blockIdx.z;
    int i0 = blockIdx.y * 128;
    int j0 = blockIdx.x * 128;

    sq[tid] = ((const float4*)(g_q + ((size_t)b * NTOK + i0) * C1))[tid];
    sk[tid] = ((const float4*)(g_k + ((size_t)b * NTOK + j0) * C1))[tid];
    __syncthreads();

    int ti = tid >> 4, tj = tid & 15;

    float4 ka[8], kb[8];
#pragma unroll
    for (int r = 0; r < 8; r++) { ka[r] = sk[(tj * 8 + r) * 2]; kb[r] = sk[(tj * 8 + r) * 2 + 1]; }

    float zc[8];
#pragma unroll
    for (int c = 0; c < 8; c++) zc[c] = 0.f;

    __half* prow = g_p + ((size_t)(b * NTOK + i0 + ti * 8)) * NTOK + j0 + tj * 8;

#pragma unroll
    for (int r = 0; r < 8; r++) {
        float4 qa = sq[(ti * 8 + r) * 2], qb = sq[(ti * 8 + r) * 2 + 1];
        float e[8];
#pragma unroll
        for (int jc = 0; jc < 8; jc++) {
            float s = qa.x * ka[jc].x + qa.y * ka[jc].y + qa.z * ka[jc].z + qa.w * ka[jc].w
                    + qb.x * kb[jc].x + qb.y * kb[jc].y + qb.z * kb[jc].z + qb.w * kb[jc].w;
            e[jc] = ex2f(fmaf(s, LOG2E, -ESH));
            zc[jc] += e[jc];
        }
        uint4 pk;
        pk.x = pack_h2(e[0], e[1]); pk.y = pack_h2(e[2], e[3]);
        pk.z = pack_h2(e[4], e[5]); pk.w = pack_h2(e[6], e[7]);
        *(uint4*)(prow + (size_t)r * NTOK) = pk;
    }

#pragma unroll
    for (int c = 0; c < 8; c++) szp[ti * 128 + c * 16 + tj] = zc[c];
    __syncthreads();

    if (tid < 128) {
        int cv = tid & 7, tjv = tid >> 3;
        float z = 0.f;
#pragma unroll
        for (int t = 0; t < 16; t++) z += szp[t * 128 + cv * 16 + tjv];
        g_zp[((size_t)blockIdx.y * BATCH + b) * NTOK + j0 + tid] = z;
    }
}

// ---------------- K3: V'^T = ((Wv Y + bv) / Z')^T  in fp16 ----------------
// grid 144 (128 tokens each), block 256: thread = (token, half-of-channels)
__global__ void vscale_kernel(const float* __restrict__ Y,
                              const float* __restrict__ Wv, const float* __restrict__ bv) {
    __shared__ float  sW[CIN * CIN];   // [c_in][o]
    __shared__ float  sZ[128], szh[128];
    __shared__ __half sT[CIN * 128];   // [c][token]
    int tid = threadIdx.x;
    int gj0 = blockIdx.x * 128;
    int b = gj0 / NTOK, j0 = gj0 - b * NTOK;

    for (int t = tid; t < CIN * CIN; t += 256) {
        int c = t >> 6, o = t & 63;
        sW[t] = Wv[o * CIN + c];
    }

    int tl = tid & 127, h = tid >> 7;

    // finalize Z for this 128-token strip (deterministic split-sum)
    {
        float zs = 0.f;
        for (int it = h * 36; it < h * 36 + 36; it++)
            zs += g_zp[((size_t)it * BATCH + b) * NTOK + j0 + tl];
        if (h == 0) sZ[tl] = zs; else szh[tl] = zs;
    }
    __syncthreads();
    if (tid < 128) sZ[tid] += szh[tid];
    __syncthreads();

    float rz = 1.0f / sZ[tl];

    float acc[32];
#pragma unroll
    for (int o = 0; o < 32; o++) acc[o] = 0.f;

    const float* Yp = Y + (size_t)b * CIN * NTOK + j0 + tl;
#pragma unroll 2
    for (int c = 0; c < CIN; c++) {
        float yv = Yp[(size_t)c * NTOK];
        const float4* w4 = (const float4*)&sW[c * CIN + h * 32];
#pragma unroll
        for (int p = 0; p < 8; p++) {
            float4 w = w4[p];
            acc[p * 4 + 0] += w.x * yv; acc[p * 4 + 1] += w.y * yv;
            acc[p * 4 + 2] += w.z * yv; acc[p * 4 + 3] += w.w * yv;
        }
    }
#pragma unroll
    for (int o = 0; o < 32; o++) {
        float v = (acc[o] + bv[h * 32 + o]) * rz;
        sT[(h * 32 + o) * 128 + tl] = __float2half(v);
    }
    __syncthreads();

    // coalesced fp16 writes: g_vt[b][c][j0..j0+128]  (64 c x 16 chunks = 1024 uint4)
#pragma unroll
    for (int t = 0; t < 4; t++) {
        int id = tid + t * 256;
        int c = id >> 4, ch = id & 15;
        uint4 v = *(const uint4*)(sT + c * 128 + ch * 8);
        *(uint4*)(g_vt + ((size_t)b * CIN + c) * NTOK + j0 + ch * 8) = v;
    }
}

// ---------------- K4: x = P' * V'  (tensor cores) + out = Y + x^T ----------------
// grid (NT128, BATCH), block 256 = 8 warps (4 M-warps x 2 N-warps)
#define K4_STAGE 24576                     // 16KB A + 8KB B per stage
#define K4_SMEM  (3 * K4_STAGE)

__global__ __launch_bounds__(256, 1) void av_kernel(const float* __restrict__ Y,
                                                    float* __restrict__ out) {
    extern __shared__ __align__(16) char sm[];
    uint32_t sbase = (uint32_t)__cvta_generic_to_shared(sm);

    int tid = threadIdx.x;
    int b = blockIdx.y;
    int i0 = blockIdx.x * 128;
    const __half* Pb = g_p  + (size_t)b * NTOK * NTOK;
    const __half* Vb = g_vt + (size_t)b * CIN * NTOK;

    int lane = tid & 31, warp = tid >> 5;
    int wm = warp >> 1, wn = warp & 1;

    // prefetch one K-chunk (KC=64) into stage s
    auto prefetch = [&](int kt, int s) {
        int k0 = kt * 64;
#pragma unroll
        for (int cc = 0; cc < 4; cc++) {                  // A: 128 rows x 8 chunks
            int id = tid + cc * 256;
            int row = id >> 3, ch = id & 7;
            cp_async16(sbase + s * K4_STAGE + row * 128 + (((ch ^ (row & 7))) << 4),
                       Pb + (size_t)(i0 + row) * NTOK + k0 + ch * 8);
        }
#pragma unroll
        for (int cc = 0; cc < 2; cc++) {                  // B: 64 rows x 8 chunks
            int id = tid + cc * 256;
            int row = id >> 3, ch = id & 7;
            cp_async16(sbase + s * K4_STAGE + 16384 + row * 128 + ((ch ^ (row & 7)) << 4),
                       Vb + (size_t)row * NTOK + k0 + ch * 8);
        }
        asm volatile("cp.async.commit_group;\n" ::: "memory");
    };

    float d[2][4][4];
#pragma unroll
    for (int mi = 0; mi < 2; mi++)
#pragma unroll
        for (int ni = 0; ni < 4; ni++)
#pragma unroll
            for (int p = 0; p < 4; p++) d[mi][ni][p] = 0.f;

    // per-lane ldmatrix row geometry
    int arow[2], brow[2];
#pragma unroll
    for (int mi = 0; mi < 2; mi++) arow[mi] = wm * 32 + mi * 16 + (lane & 15);
#pragma unroll
    for (int nb = 0; nb < 2; nb++)
        brow[nb] = wn * 32 + nb * 16 + ((lane >> 4) << 3) + (lane & 7);
    int achs = lane >> 4;          // A k-chunk select
    int bchs = (lane >> 3) & 1;    // B k-chunk select

    prefetch(0, 0);
    prefetch(1, 1);

    for (int kt = 0; kt < NKC; kt++) {
        int s = kt % 3;
        if (kt + 2 < NKC) prefetch(kt + 2, (kt + 2) % 3);
        if (kt < NKC - 2)      asm volatile("cp.async.wait_group 2;\n" ::: "memory");
        else if (kt == NKC - 2) asm volatile("cp.async.wait_group 1;\n" ::: "memory");
        else                    asm volatile("cp.async.wait_group 0;\n" ::: "memory");
        __syncthreads();

        uint32_t aBase = sbase + s * K4_STAGE;
        uint32_t bBase = aBase + 16384;
#pragma unroll
        for (int ks = 0; ks < 4; ks++) {
            uint32_t a[2][4], br[2][4];
#pragma unroll
            for (int mi = 0; mi < 2; mi++) {
                int ch = ks * 2 + achs;
                ldsm4(a[mi][0], a[mi][1], a[mi][2], a[mi][3],
                      aBase + arow[mi] * 128 + ((ch ^ (arow[mi] & 7)) << 4));
            }
#pragma unroll
            for (int nb = 0; nb < 2; nb++) {
                int ch = ks * 2 + bchs;
                ldsm4(br[nb][0], br[nb][1], br[nb][2], br[nb][3],
                      bBase + brow[nb] * 128 + ((ch ^ (brow[nb] & 7)) << 4));
            }
#pragma unroll
            for (int mi = 0; mi < 2; mi++) {
#pragma unroll
                for (int ni = 0; ni < 4; ni++) {
                    int nb = ni >> 1, sub = ni & 1;
                    mma16816(d[mi][ni][0], d[mi][ni][1], d[mi][ni][2], d[mi][ni][3],
                             a[mi][0], a[mi][1], a[mi][2], a[mi][3],
                             br[nb][sub * 2], br[nb][sub * 2 + 1]);
                }
            }
        }
        __syncthreads();
    }

    // epilogue: transpose via padded smem, fuse residual
    float* sX = (float*)sm;                 // [64][132]
    __syncthreads();
#pragma unroll
    for (int mi = 0; mi < 2; mi++) {
#pragma unroll
        for (int ni = 0; ni < 4; ni++) {
            int r = wm * 32 + mi * 16 + (lane >> 2);
            int c = wn * 32 + ni * 8 + (lane & 3) * 2;
            sX[c * 132 + r]             = d[mi][ni][0];
            sX[(c + 1) * 132 + r]       = d[mi][ni][1];
            sX[c * 132 + r + 8]         = d[mi][ni][2];
            sX[(c + 1) * 132 + r + 8]   = d[mi][ni][3];
        }
    }
    __syncthreads();

    const float* Yb = Y + (size_t)b * CIN * NTOK + i0;
    float* ob = out + (size_t)b * CIN * NTOK + i0;
#pragma unroll
    for (int t = 0; t < 8; t++) {
        int id = tid + t * 256;             // 2048 float4s
        int c = id >> 5, q4 = id & 31;
        const float* sp = sX + c * 132 + q4 * 4;
        float4 yv = *(const float4*)(Yb + (size_t)c * NTOK + q4 * 4);
        float4 o;
        o.x = yv.x + sp[0]; o.y = yv.y + sp[1]; o.z = yv.z + sp[2]; o.w = yv.w + sp[3];
        *(float4*)(ob + (size_t)c * NTOK + q4 * 4) = o;
    }
}

// ---------------- launch ----------------
extern "C" void kernel_launch(void* const* d_in, const int* in_sizes, int n_in,
                              void* d_out, int out_size) {
    const float* X  = (const float*)d_in[0];
    const float* Y  = (const float*)d_in[1];
    const float* Wq = (const float*)d_in[2];
    const float* bq = (const float*)d_in[3];
    const float* Wk = (const float*)d_in[4];
    const float* bk = (const float*)d_in[5];
    const float* Wv = (const float*)d_in[6];
    const float* bv = (const float*)d_in[7];
    float* out = (float*)d_out;

    cudaFuncSetAttribute(av_kernel, cudaFuncAttributeMaxDynamicSharedMemorySize, K4_SMEM);

    qk_kernel<<<BATCH * NTOK / 128, 128>>>(X, Wq, bq, Wk, bk);
    pexp_kernel<<<dim3(NT128, NT128, BATCH), 256>>>();
    vscale_kernel<<<BATCH * NTOK / 128, 256>>>(Y, Wv, bv);
    av_kernel<<<dim3(NT128, BATCH), 256, K4_SMEM>>>(Y, out);
}

// round 4
// speedup vs baseline: 7.1104x; 1.5715x over previous
#include <cuda_runtime.h>
#include <cuda_fp16.h>
#include <cstdint>

#define BATCH 2
#define CIN   64
#define NTOK  9216
#define C1    8
#define NT128 72                  // NTOK / 128
#define NKC   144                 // NTOK / 64  (j-chunks in fused kernel)
#define LOG2E 1.4426950408889634f
#define ESH   5.770780163555854f  // 4 * log2(e)

// ---------------- scratch ----------------
__device__ float  g_q [BATCH * NTOK * C1];
__device__ float  g_k [BATCH * NTOK * C1];
__device__ __half g_kh[BATCH * NTOK * C1];    // fp16 copy of k, [b][j][8]
__device__ __half g_vt[BATCH * CIN * NTOK];   // V'^T fp16: [b][c][j], prescaled by 1/Z
__device__ float  g_z [BATCH * NTOK];

// ---------------- PTX helpers ----------------
__device__ __forceinline__ float ex2f(float x) {
    float r; asm("ex2.approx.f32 %0, %1;" : "=f"(r) : "f"(x)); return r;
}
__device__ __forceinline__ uint32_t pack_h2(float lo, float hi) {
    uint32_t r; asm("cvt.rn.f16x2.f32 %0, %1, %2;" : "=r"(r) : "f"(hi), "f"(lo)); return r;
}
__device__ __forceinline__ void ffma2(unsigned long long& d,
                                      unsigned long long a, unsigned long long b) {
    asm volatile("fma.rn.f32x2 %0, %1, %2, %0;" : "+l"(d) : "l"(a), "l"(b));
}
__device__ __forceinline__ void unpack2(float& lo, float& hi, unsigned long long v) {
    asm("mov.b64 {%0, %1}, %2;" : "=f"(lo), "=f"(hi) : "l"(v));
}
__device__ __forceinline__ void cp_async16(uint32_t saddr, const void* g) {
    asm volatile("cp.async.cg.shared.global [%0], [%1], 16;\n" :: "r"(saddr), "l"(g));
}
__device__ __forceinline__ void ldsm4(uint32_t& r0, uint32_t& r1, uint32_t& r2, uint32_t& r3,
                                      uint32_t a) {
    asm volatile("ldmatrix.sync.aligned.m8n8.x4.shared.b16 {%0,%1,%2,%3}, [%4];"
                 : "=r"(r0), "=r"(r1), "=r"(r2), "=r"(r3) : "r"(a));
}
__device__ __forceinline__ void mma16816(float& d0, float& d1, float& d2, float& d3,
                                         uint32_t a0, uint32_t a1, uint32_t a2, uint32_t a3,
                                         uint32_t b0, uint32_t b1) {
    asm volatile(
        "mma.sync.aligned.m16n8k16.row.col.f32.f16.f16.f32 "
        "{%0,%1,%2,%3}, {%4,%5,%6,%7}, {%8,%9}, {%0,%1,%2,%3};"
        : "+f"(d0), "+f"(d1), "+f"(d2), "+f"(d3)
        : "r"(a0), "r"(a1), "r"(a2), "r"(a3), "r"(b0), "r"(b1));
}
__device__ __forceinline__ void mma1688(float& d0, float& d1, float& d2, float& d3,
                                        uint32_t a0, uint32_t a1, uint32_t b0) {
    asm volatile(
        "mma.sync.aligned.m16n8k8.row.col.f32.f16.f16.f32 "
        "{%0,%1,%2,%3}, {%4,%5}, {%6}, {%0,%1,%2,%3};"
        : "+f"(d0), "+f"(d1), "+f"(d2), "+f"(d3)
        : "r"(a0), "r"(a1), "r"(b0));
}

// ---------------- K1: q,k 1x1 convs (+ fp16 K copy) ----------------
__global__ void qk_kernel(const float* __restrict__ X,
                          const float* __restrict__ Wq, const float* __restrict__ bq,
                          const float* __restrict__ Wk, const float* __restrict__ bk) {
    __shared__ float sW[16 * CIN];   // [c][o]: o 0-7 = Wq rows, 8-15 = Wk rows
    int tid = threadIdx.x;
    for (int t = tid; t < 16 * CIN; t += 128) {
        int c = t >> 4, o = t & 15;
        sW[t] = (o < 8) ? Wq[o * CIN + c] : Wk[(o - 8) * CIN + c];
    }
    __syncthreads();

    int gi = blockIdx.x * 128 + tid;
    int b = gi / NTOK, i = gi - b * NTOK;
    const float* Xp = X + (size_t)b * CIN * NTOK + i;

    float acc[16];
#pragma unroll
    for (int o = 0; o < 16; o++) acc[o] = 0.f;

#pragma unroll 8
    for (int c = 0; c < CIN; c++) {
        float xv = Xp[(size_t)c * NTOK];
        const float4* w4 = (const float4*)&sW[c * 16];
        float4 w0 = w4[0], w1 = w4[1], w2 = w4[2], w3 = w4[3];
        acc[0] += w0.x * xv; acc[1] += w0.y * xv; acc[2] += w0.z * xv; acc[3] += w0.w * xv;
        acc[4] += w1.x * xv; acc[5] += w1.y * xv; acc[6] += w1.z * xv; acc[7] += w1.w * xv;
        acc[8] += w2.x * xv; acc[9] += w2.y * xv; acc[10] += w2.z * xv; acc[11] += w2.w * xv;
        acc[12] += w3.x * xv; acc[13] += w3.y * xv; acc[14] += w3.z * xv; acc[15] += w3.w * xv;
    }

    float kq[16];
#pragma unroll
    for (int o = 0; o < 8; o++) { kq[o] = acc[o] + bq[o]; kq[8 + o] = acc[8 + o] + bk[o]; }

    float4* qp = (float4*)(g_q + (size_t)gi * C1);
    float4* kp = (float4*)(g_k + (size_t)gi * C1);
    qp[0] = make_float4(kq[0], kq[1], kq[2], kq[3]);
    qp[1] = make_float4(kq[4], kq[5], kq[6], kq[7]);
    kp[0] = make_float4(kq[8], kq[9], kq[10], kq[11]);
    kp[1] = make_float4(kq[12], kq[13], kq[14], kq[15]);
    uint4 khp;
    khp.x = pack_h2(kq[8], kq[9]);  khp.y = pack_h2(kq[10], kq[11]);
    khp.z = pack_h2(kq[12], kq[13]); khp.w = pack_h2(kq[14], kq[15]);
    *(uint4*)(g_kh + (size_t)gi * C1) = khp;
}

// ---------------- K2: Z_j = sum_i exp(q_i.k_j - 4) ----------------
// grid = BATCH * 144 (64-j strips), block 256; rep = 4-way i split per strip
__global__ void zsum_kernel() {
    __shared__ float4 sq[512];            // 256 i's * 8 floats
    __shared__ float  zred[4][64];
    int tid = threadIdx.x;
    int b  = blockIdx.x / (NTOK / 64);
    int j0 = (blockIdx.x - b * (NTOK / 64)) * 64;
    int jl  = tid & 63;
    int rep = tid >> 6;

    const ulonglong2* kp2 = (const ulonglong2*)(g_k + ((size_t)b * NTOK + j0 + jl) * C1);
    ulonglong2 k01 = kp2[0], k23 = kp2[1];
    const float4* qbase = (const float4*)(g_q + (size_t)b * NTOK * C1);

    float zacc = 0.f;
    for (int it = 0; it < NTOK; it += 256) {
        sq[tid]       = qbase[it * 2 + tid];
        sq[tid + 256] = qbase[it * 2 + tid + 256];
        __syncthreads();
#pragma unroll 8
        for (int ii = rep; ii < 256; ii += 4) {
            ulonglong2 q01 = *(const ulonglong2*)&sq[ii * 2];
            ulonglong2 q23 = *(const ulonglong2*)&sq[ii * 2 + 1];
            unsigned long long s2 = 0ULL;
            ffma2(s2, q01.x, k01.x); ffma2(s2, q01.y, k01.y);
            ffma2(s2, q23.x, k23.x); ffma2(s2, q23.y, k23.y);
            float lo, hi; unpack2(lo, hi, s2);
            zacc += ex2f(fmaf(lo + hi, LOG2E, -ESH));
        }
        __syncthreads();
    }
    zred[rep][jl] = zacc;
    __syncthreads();
    if (tid < 64)
        g_z[(size_t)b * NTOK + j0 + tid] =
            zred[0][tid] + zred[1][tid] + zred[2][tid] + zred[3][tid];
}

// ---------------- K3: V'^T = ((Wv Y + bv) / Z)^T fp16 ----------------
__global__ void vscale_kernel(const float* __restrict__ Y,
                              const float* __restrict__ Wv, const float* __restrict__ bv) {
    __shared__ float  sW[CIN * CIN];   // [c_in][o]
    __shared__ __half sT[CIN * 128];   // [c][token]
    int tid = threadIdx.x;
    int gj0 = blockIdx.x * 128;
    int b = gj0 / NTOK, j0 = gj0 - b * NTOK;

    for (int t = tid; t < CIN * CIN; t += 256) {
        int c = t >> 6, o = t & 63;
        sW[t] = Wv[o * CIN + c];
    }
    __syncthreads();

    int tl = tid & 127, h = tid >> 7;
    float rz = 1.0f / g_z[(size_t)b * NTOK + j0 + tl];

    float acc[32];
#pragma unroll
    for (int o = 0; o < 32; o++) acc[o] = 0.f;

    const float* Yp = Y + (size_t)b * CIN * NTOK + j0 + tl;
#pragma unroll 2
    for (int c = 0; c < CIN; c++) {
        float yv = Yp[(size_t)c * NTOK];
        const float4* w4 = (const float4*)&sW[c * CIN + h * 32];
#pragma unroll
        for (int p = 0; p < 8; p++) {
            float4 w = w4[p];
            acc[p * 4 + 0] += w.x * yv; acc[p * 4 + 1] += w.y * yv;
            acc[p * 4 + 2] += w.z * yv; acc[p * 4 + 3] += w.w * yv;
        }
    }
#pragma unroll
    for (int o = 0; o < 32; o++)
        sT[(h * 32 + o) * 128 + tl] = __float2half((acc[o] + bv[h * 32 + o]) * rz);
    __syncthreads();

#pragma unroll
    for (int t = 0; t < 4; t++) {
        int id = tid + t * 256;
        int c = id >> 4, ch = id & 15;
        uint4 v = *(const uint4*)(sT + c * 128 + ch * 8);
        *(uint4*)(g_vt + ((size_t)b * CIN + c) * NTOK + j0 + ch * 8) = v;
    }
}

// ---------------- K4: fused x = softmax-recompute * V' + residual ----------------
// grid (NT128, BATCH), 256 thr = 8 warps; warp w owns rows i0 + w*16 .. +16.
// Per 64-j chunk: S = Q Kh^T via mma.m16n8k8 (Q frags persistent in regs),
// exp in regs, fragment-identity repack -> A of m16n8k16 AV MMA.
#define AV_VSTAGE 8192                       // 64 c-rows x 128B
#define AV_KOFF   16384                      // after 2 V stages
#define AV_KSTAGE 1024                       // 64 j x 16B
#define AV_SMEM   34048                      // >= max(18KB pipeline, 64*132*4 epilogue)

__global__ __launch_bounds__(256, 1) void av2_kernel(const float* __restrict__ Y,
                                                     float* __restrict__ out) {
    extern __shared__ __align__(16) char sm[];
    uint32_t sbase = (uint32_t)__cvta_generic_to_shared(sm);

    int tid = threadIdx.x;
    int lane = tid & 31, warp = tid >> 5;
    int b = blockIdx.y;
    int i0 = blockIdx.x * 128;

    const __half* Vb = g_vt + (size_t)b * CIN * NTOK;
    const uint4*  Kh = (const uint4*)(g_kh + (size_t)b * NTOK * C1);

    // persistent Q A-fragments (m16k8): rows warp*16 + lane/4 (+8), k pair 2*(lane&3)
    int qrow = i0 + warp * 16 + (lane >> 2);
    int kp   = (lane & 3) * 2;
    const float* qb = g_q + (size_t)b * NTOK * C1;
    uint32_t aq0 = pack_h2(qb[(size_t)qrow * C1 + kp], qb[(size_t)qrow * C1 + kp + 1]);
    uint32_t aq1 = pack_h2(qb[(size_t)(qrow + 8) * C1 + kp], qb[(size_t)(qrow + 8) * C1 + kp + 1]);

    auto prefetch = [&](int kt, int s) {
        int j0 = kt * 64;
#pragma unroll
        for (int cc = 0; cc < 2; cc++) {                 // V: 64 rows(c) x 8 chunks
            int id = tid + cc * 256;
            int row = id >> 3, ch = id & 7;
            cp_async16(sbase + s * AV_VSTAGE + row * 128 + ((ch ^ (row & 7)) << 4),
                       Vb + (size_t)row * NTOK + j0 + ch * 8);
        }
        if (tid < 64)                                    // Kh: 64 j x 16B
            cp_async16(sbase + AV_KOFF + s * AV_KSTAGE + tid * 16, Kh + j0 + tid);
        asm volatile("cp.async.commit_group;\n" ::: "memory");
    };

    float d[8][4];
#pragma unroll
    for (int ni = 0; ni < 8; ni++)
#pragma unroll
        for (int p = 0; p < 4; p++) d[ni][p] = 0.f;

    int brow[4];
#pragma unroll
    for (int nb = 0; nb < 4; nb++)
        brow[nb] = nb * 16 + ((lane >> 4) << 3) + (lane & 7);
    int bchs = (lane >> 3) & 1;
    uint32_t kfoff = (lane >> 2) * 16 + (lane & 3) * 4;   // b-frag addr within K stage

    prefetch(0, 0);

    for (int kt = 0; kt < NKC; kt++) {
        int s = kt & 1;
        if (kt + 1 < NKC) prefetch(kt + 1, (kt + 1) & 1);
        if (kt + 1 < NKC) asm volatile("cp.async.wait_group 1;\n" ::: "memory");
        else              asm volatile("cp.async.wait_group 0;\n" ::: "memory");
        __syncthreads();

        // ---- S = Q K^T (8 n8-tiles), exp, repack to P A-frags ----
        uint32_t pa[4][4];
        uint32_t kBase = sbase + AV_KOFF + s * AV_KSTAGE;
#pragma unroll
        for (int t = 0; t < 8; t++) {
            uint32_t bfrag = *(const uint32_t*)(sm + (kBase - sbase) + t * 128 + kfoff);
            float c0 = 0.f, c1 = 0.f, c2 = 0.f, c3 = 0.f;
            mma1688(c0, c1, c2, c3, aq0, aq1, bfrag);
            float e0 = ex2f(fmaf(c0, LOG2E, -ESH));
            float e1 = ex2f(fmaf(c1, LOG2E, -ESH));
            float e2 = ex2f(fmaf(c2, LOG2E, -ESH));
            float e3 = ex2f(fmaf(c3, LOG2E, -ESH));
            pa[t >> 1][(t & 1) * 2 + 0] = pack_h2(e0, e1);
            pa[t >> 1][(t & 1) * 2 + 1] = pack_h2(e2, e3);
        }

        // ---- AV: d += P(16x64) * V'(64x64) ----
        uint32_t vBase = sbase + s * AV_VSTAGE;
#pragma unroll
        for (int ks = 0; ks < 4; ks++) {
            uint32_t br[4][4];
            int ch = ks * 2 + bchs;
#pragma unroll
            for (int nb = 0; nb < 4; nb++)
                ldsm4(br[nb][0], br[nb][1], br[nb][2], br[nb][3],
                      vBase + brow[nb] * 128 + ((ch ^ (brow[nb] & 7)) << 4));
#pragma unroll
            for (int ni = 0; ni < 8; ni++) {
                int nb = ni >> 1, sub = ni & 1;
                mma16816(d[ni][0], d[ni][1], d[ni][2], d[ni][3],
                         pa[ks][0], pa[ks][1], pa[ks][2], pa[ks][3],
                         br[nb][sub * 2], br[nb][sub * 2 + 1]);
            }
        }
        __syncthreads();
    }

    // ---- epilogue: transpose via padded smem, fuse residual ----
    float* sX = (float*)sm;                 // [64 c][132]
#pragma unroll
    for (int ni = 0; ni < 8; ni++) {
        int r = warp * 16 + (lane >> 2);
        int c = ni * 8 + (lane & 3) * 2;
        sX[c * 132 + r]           = d[ni][0];
        sX[(c + 1) * 132 + r]     = d[ni][1];
        sX[c * 132 + r + 8]       = d[ni][2];
        sX[(c + 1) * 132 + r + 8] = d[ni][3];
    }
    __syncthreads();

    const float* Yb = Y + (size_t)b * CIN * NTOK + i0;
    float* ob = out + (size_t)b * CIN * NTOK + i0;
#pragma unroll
    for (int t = 0; t < 8; t++) {
        int id = tid + t * 256;             // 2048 float4s
        int c = id >> 5, q4 = id & 31;
        const float* sp = sX + c * 132 + q4 * 4;
        float4 yv = *(const float4*)(Yb + (size_t)c * NTOK + q4 * 4);
        float4 o;
        o.x = yv.x + sp[0]; o.y = yv.y + sp[1]; o.z = yv.z + sp[2]; o.w = yv.w + sp[3];
        *(float4*)(ob + (size_t)c * NTOK + q4 * 4) = o;
    }
}

// ---------------- launch ----------------
extern "C" void kernel_launch(void* const* d_in, const int* in_sizes, int n_in,
                              void* d_out, int out_size) {
    const float* X  = (const float*)d_in[0];
    const float* Y  = (const float*)d_in[1];
    const float* Wq = (const float*)d_in[2];
    const float* bq = (const float*)d_in[3];
    const float* Wk = (const float*)d_in[4];
    const float* bk = (const float*)d_in[5];
    const float* Wv = (const float*)d_in[6];
    const float* bv = (const float*)d_in[7];
    float* out = (float*)d_out;

    cudaFuncSetAttribute(av2_kernel, cudaFuncAttributeMaxDynamicSharedMemorySize, AV_SMEM);

    qk_kernel<<<BATCH * NTOK / 128, 128>>>(X, Wq, bq, Wk, bk);
    zsum_kernel<<<BATCH * (NTOK / 64), 256>>>();
    vscale_kernel<<<BATCH * NTOK / 128, 256>>>(Y, Wv, bv);
    av2_kernel<<<dim3(NT128, BATCH), 256, AV_SMEM>>>(Y, out);
}

// round 5
// speedup vs baseline: 10.2885x; 1.4470x over previous
#include <cuda_runtime.h>
#include <cuda_fp16.h>
#include <cstdint>

#define BATCH 2
#define CIN   64
#define NTOK  9216
#define C1    8
#define NT128 72                  // NTOK / 128
#define NKC   144                 // NTOK / 64
#define LOG2E 1.4426950408889634f
#define ESH   5.770780163555854f  // 4 * log2(e)

// ---------------- scratch ----------------
__device__ float  g_q [BATCH * NTOK * C1];
__device__ __half g_qh[BATCH * NTOK * C1];    // fp16(q * LOG2E)
__device__ __half g_kh[BATCH * NTOK * C1];    // fp16(k)
__device__ __half g_vt[BATCH * CIN * NTOK];   // V'^T fp16: [b][c][j], scaled by 1/64
__device__ float  g_sh[BATCH * NTOK];         // per-j exp2 shift: 6 - ESH - log2(Z')

// ---------------- PTX helpers ----------------
__device__ __forceinline__ uint32_t pack_h2(float lo, float hi) {
    uint32_t r; asm("cvt.rn.f16x2.f32 %0, %1, %2;" : "=r"(r) : "f"(hi), "f"(lo)); return r;
}
__device__ __forceinline__ uint32_t hex2(uint32_t h) {
    uint32_t r; asm("ex2.approx.f16x2 %0, %1;" : "=r"(r) : "r"(h)); return r;
}
__device__ __forceinline__ uint32_t hadd2u(uint32_t a, uint32_t b) {
    uint32_t r; asm("add.f16x2 %0, %1, %2;" : "=r"(r) : "r"(a), "r"(b)); return r;
}
__device__ __forceinline__ float2 h2f2(uint32_t h) {
    float a, b;
    asm("{.reg .f16 l, u; mov.b32 {l, u}, %2; cvt.f32.f16 %0, l; cvt.f32.f16 %1, u;}"
        : "=f"(a), "=f"(b) : "r"(h));
    return make_float2(a, b);
}
__device__ __forceinline__ float lg2f(float x) {
    float r; asm("lg2.approx.f32 %0, %1;" : "=f"(r) : "f"(x)); return r;
}
__device__ __forceinline__ void cp_async16(uint32_t saddr, const void* g) {
    asm volatile("cp.async.cg.shared.global [%0], [%1], 16;\n" :: "r"(saddr), "l"(g));
}
__device__ __forceinline__ void ldsm4(uint32_t& r0, uint32_t& r1, uint32_t& r2, uint32_t& r3,
                                      uint32_t a) {
    asm volatile("ldmatrix.sync.aligned.m8n8.x4.shared.b16 {%0,%1,%2,%3}, [%4];"
                 : "=r"(r0), "=r"(r1), "=r"(r2), "=r"(r3) : "r"(a));
}
__device__ __forceinline__ void mma16816(float& d0, float& d1, float& d2, float& d3,
                                         uint32_t a0, uint32_t a1, uint32_t a2, uint32_t a3,
                                         uint32_t b0, uint32_t b1) {
    asm volatile(
        "mma.sync.aligned.m16n8k16.row.col.f32.f16.f16.f32 "
        "{%0,%1,%2,%3}, {%4,%5,%6,%7}, {%8,%9}, {%0,%1,%2,%3};"
        : "+f"(d0), "+f"(d1), "+f"(d2), "+f"(d3)
        : "r"(a0), "r"(a1), "r"(a2), "r"(a3), "r"(b0), "r"(b1));
}
__device__ __forceinline__ void mma1688(float& d0, float& d1, float& d2, float& d3,
                                        uint32_t a0, uint32_t a1, uint32_t b0) {
    asm volatile(
        "mma.sync.aligned.m16n8k8.row.col.f32.f16.f16.f32 "
        "{%0,%1,%2,%3}, {%4,%5}, {%6}, {%0,%1,%2,%3};"
        : "+f"(d0), "+f"(d1), "+f"(d2), "+f"(d3)
        : "r"(a0), "r"(a1), "r"(b0));
}

// ---------------- K1: q,k 1x1 convs (+ fp16 copies) ----------------
__global__ void qk_kernel(const float* __restrict__ X,
                          const float* __restrict__ Wq, const float* __restrict__ bq,
                          const float* __restrict__ Wk, const float* __restrict__ bk) {
    __shared__ float sW[16 * CIN];   // [c][o]: o 0-7 = Wq rows, 8-15 = Wk rows
    int tid = threadIdx.x;
    for (int t = tid; t < 16 * CIN; t += 128) {
        int c = t >> 4, o = t & 15;
        sW[t] = (o < 8) ? Wq[o * CIN + c] : Wk[(o - 8) * CIN + c];
    }
    __syncthreads();

    int gi = blockIdx.x * 128 + tid;
    int b = gi / NTOK;
    const float* Xp = X + (size_t)b * CIN * NTOK + (gi - b * NTOK);

    float acc[16];
#pragma unroll
    for (int o = 0; o < 16; o++) acc[o] = 0.f;

#pragma unroll 16
    for (int c = 0; c < CIN; c++) {
        float xv = Xp[(size_t)c * NTOK];
        const float4* w4 = (const float4*)&sW[c * 16];
        float4 w0 = w4[0], w1 = w4[1], w2 = w4[2], w3 = w4[3];
        acc[0] += w0.x * xv; acc[1] += w0.y * xv; acc[2] += w0.z * xv; acc[3] += w0.w * xv;
        acc[4] += w1.x * xv; acc[5] += w1.y * xv; acc[6] += w1.z * xv; acc[7] += w1.w * xv;
        acc[8] += w2.x * xv; acc[9] += w2.y * xv; acc[10] += w2.z * xv; acc[11] += w2.w * xv;
        acc[12] += w3.x * xv; acc[13] += w3.y * xv; acc[14] += w3.z * xv; acc[15] += w3.w * xv;
    }

    float q[8], k[8];
#pragma unroll
    for (int o = 0; o < 8; o++) { q[o] = acc[o] + bq[o]; k[o] = acc[8 + o] + bk[o]; }

    float4* qp = (float4*)(g_q + (size_t)gi * C1);
    qp[0] = make_float4(q[0], q[1], q[2], q[3]);
    qp[1] = make_float4(q[4], q[5], q[6], q[7]);
    uint4 qh, kh;
    qh.x = pack_h2(q[0] * LOG2E, q[1] * LOG2E); qh.y = pack_h2(q[2] * LOG2E, q[3] * LOG2E);
    qh.z = pack_h2(q[4] * LOG2E, q[5] * LOG2E); qh.w = pack_h2(q[6] * LOG2E, q[7] * LOG2E);
    *(uint4*)(g_qh + (size_t)gi * C1) = qh;
    kh.x = pack_h2(k[0], k[1]); kh.y = pack_h2(k[2], k[3]);
    kh.z = pack_h2(k[4], k[5]); kh.w = pack_h2(k[6], k[7]);
    *(uint4*)(g_kh + (size_t)gi * C1) = kh;
}

// ---------------- K2: tensor-core Z + shift ----------------
// grid 144 (128-j strips), block 256 = 8 warps x 16 j rows. Loop i in 64-chunks.
// S^T = Kh * Qh^T via mma.m16n8k8 (Kh frags persistent), hex2, row-sum.
__global__ __launch_bounds__(256, 1) void zsum_kernel() {
    __shared__ __align__(16) char sm[2 * 1024];          // 2-stage Qh: 64 i x 16B
    uint32_t sbase = (uint32_t)__cvta_generic_to_shared(sm);
    int tid = threadIdx.x, lane = tid & 31, warp = tid >> 5;
    int b = blockIdx.x / NT128;
    int j0 = (blockIdx.x - b * NT128) * 128;

    int jrow = j0 + warp * 16 + (lane >> 2);
    const char* khb = (const char*)(g_kh + (size_t)b * NTOK * C1);
    uint32_t a0 = *(const uint32_t*)(khb + (size_t)jrow * 16 + (lane & 3) * 4);
    uint32_t a1 = *(const uint32_t*)(khb + (size_t)(jrow + 8) * 16 + (lane & 3) * 4);

    const uint4* Qh = (const uint4*)(g_qh + (size_t)b * NTOK * C1);
    auto prefetch = [&](int ct, int s) {
        if (tid < 64) cp_async16(sbase + s * 1024 + tid * 16, Qh + ct * 64 + tid);
        asm volatile("cp.async.commit_group;\n" ::: "memory");
    };

    uint32_t kfoff = (lane >> 2) * 16 + (lane & 3) * 4;
    float zfA = 0.f, zfB = 0.f;

    prefetch(0, 0);
    for (int ct = 0; ct < NKC; ct++) {
        int s = ct & 1;
        if (ct + 1 < NKC) prefetch(ct + 1, s ^ 1);
        if (ct + 1 < NKC) asm volatile("cp.async.wait_group 1;\n" ::: "memory");
        else              asm volatile("cp.async.wait_group 0;\n" ::: "memory");
        __syncthreads();

        uint32_t zA = 0, zB = 0;                         // half2 accumulators
#pragma unroll
        for (int t = 0; t < 8; t++) {
            uint32_t bfrag = *(const uint32_t*)(sm + s * 1024 + t * 128 + kfoff);
            float c0 = 0.f, c1 = 0.f, c2 = 0.f, c3 = 0.f;
            mma1688(c0, c1, c2, c3, a0, a1, bfrag);
            zA = hadd2u(zA, hex2(pack_h2(c0 - ESH, c1 - ESH)));
            zB = hadd2u(zB, hex2(pack_h2(c2 - ESH, c3 - ESH)));
        }
        float2 fa = h2f2(zA), fb = h2f2(zB);
        zfA += fa.x + fa.y;
        zfB += fb.x + fb.y;
        __syncthreads();
    }

    // reduce over the 4 lanes sharing a row (lane bits 0-1 vary the i-col)
    zfA += __shfl_xor_sync(0xffffffffu, zfA, 1);
    zfA += __shfl_xor_sync(0xffffffffu, zfA, 2);
    zfB += __shfl_xor_sync(0xffffffffu, zfB, 1);
    zfB += __shfl_xor_sync(0xffffffffu, zfB, 2);
    if ((lane & 3) == 0) {
        g_sh[(size_t)b * NTOK + jrow]     = 6.0f - ESH - lg2f(zfA);
        g_sh[(size_t)b * NTOK + jrow + 8] = 6.0f - ESH - lg2f(zfB);
    }
}

// ---------------- K3: V'^T = (Wv Y + bv)^T / 64  fp16 ----------------
__global__ void vscale_kernel(const float* __restrict__ Y,
                              const float* __restrict__ Wv, const float* __restrict__ bv) {
    __shared__ float  sW[CIN * CIN];   // [c_in][o]
    __shared__ __half sT[CIN * 128];   // [c][token]
    int tid = threadIdx.x;
    int gj0 = blockIdx.x * 128;
    int b = gj0 / NTOK, j0 = gj0 - b * NTOK;

    for (int t = tid; t < CIN * CIN; t += 256) {
        int c = t >> 6, o = t & 63;
        sW[t] = Wv[o * CIN + c];
    }
    __syncthreads();

    int tl = tid & 127, h = tid >> 7;

    float acc[32];
#pragma unroll
    for (int o = 0; o < 32; o++) acc[o] = 0.f;

    const float* Yp = Y + (size_t)b * CIN * NTOK + j0 + tl;
#pragma unroll 2
    for (int c = 0; c < CIN; c++) {
        float yv = Yp[(size_t)c * NTOK];
        const float4* w4 = (const float4*)&sW[c * CIN + h * 32];
#pragma unroll
        for (int p = 0; p < 8; p++) {
            float4 w = w4[p];
            acc[p * 4 + 0] += w.x * yv; acc[p * 4 + 1] += w.y * yv;
            acc[p * 4 + 2] += w.z * yv; acc[p * 4 + 3] += w.w * yv;
        }
    }
#pragma unroll
    for (int o = 0; o < 32; o++)
        sT[(h * 32 + o) * 128 + tl] = __float2half((acc[o] + bv[h * 32 + o]) * 0.015625f);
    __syncthreads();

#pragma unroll
    for (int t = 0; t < 4; t++) {
        int id = tid + t * 256;
        int c = id >> 4, ch = id & 15;
        uint4 v = *(const uint4*)(sT + c * 128 + ch * 8);
        *(uint4*)(g_vt + ((size_t)b * CIN + c) * NTOK + j0 + ch * 8) = v;
    }
}

// ---------------- K4: fused softmax-recompute * V' + residual ----------------
// 512 thr = 16 warps; warp (wm, wj): rows i0+wm*16, j-half wj of each 64-chunk.
#define AV_VSTAGE 8192                       // 64 c-rows x 128B
#define AV_KOFF   16384
#define AV_KSTAGE 1024                       // Kh: 64 j x 16B
#define AV_SHOFF  18432
#define AV_SHSTAGE 256                       // sh: 64 j x 4B
#define AV_SMEM   34048                      // >= 64*132*4 epilogue

__global__ __launch_bounds__(512, 1) void av2_kernel(const float* __restrict__ Y,
                                                     float* __restrict__ out) {
    extern __shared__ __align__(16) char sm[];
    uint32_t sbase = (uint32_t)__cvta_generic_to_shared(sm);

    int tid = threadIdx.x, lane = tid & 31, warp = tid >> 5;
    int wm = warp >> 1, wj = warp & 1;
    int b = blockIdx.y;
    int i0 = blockIdx.x * 128;

    const __half* Vb = g_vt + (size_t)b * CIN * NTOK;
    const uint4*  Kh = (const uint4*)(g_kh + (size_t)b * NTOK * C1);
    const float*  shb = g_sh + (size_t)b * NTOK;

    // persistent Q A-fragments (m16k8), scaled by log2(e)
    int qrow = i0 + wm * 16 + (lane >> 2);
    int kp   = (lane & 3) * 2;
    const float* qb = g_q + (size_t)b * NTOK * C1;
    uint32_t aq0 = pack_h2(qb[(size_t)qrow * C1 + kp] * LOG2E,
                           qb[(size_t)qrow * C1 + kp + 1] * LOG2E);
    uint32_t aq1 = pack_h2(qb[(size_t)(qrow + 8) * C1 + kp] * LOG2E,
                           qb[(size_t)(qrow + 8) * C1 + kp + 1] * LOG2E);

    auto prefetch = [&](int kt, int s) {
        int j0 = kt * 64;
        int row = tid >> 3, ch = tid & 7;                // V: 512 x 16B
        cp_async16(sbase + s * AV_VSTAGE + row * 128 + ((ch ^ (row & 7)) << 4),
                   Vb + (size_t)row * NTOK + j0 + ch * 8);
        if (tid < 64)
            cp_async16(sbase + AV_KOFF + s * AV_KSTAGE + tid * 16, Kh + j0 + tid);
        else if (tid < 80)
            cp_async16(sbase + AV_SHOFF + s * AV_SHSTAGE + (tid - 64) * 16,
                       shb + j0 + (tid - 64) * 4);
        asm volatile("cp.async.commit_group;\n" ::: "memory");
    };

    float d[8][4];
#pragma unroll
    for (int ni = 0; ni < 8; ni++)
#pragma unroll
        for (int p = 0; p < 4; p++) d[ni][p] = 0.f;

    int brow[4];
#pragma unroll
    for (int nb = 0; nb < 4; nb++)
        brow[nb] = nb * 16 + ((lane >> 4) << 3) + (lane & 7);
    int bchs = (lane >> 3) & 1;
    uint32_t kfoff  = (lane >> 2) * 16 + (lane & 3) * 4;
    uint32_t shloff = (lane & 3) * 8;

    prefetch(0, 0);

    for (int kt = 0; kt < NKC; kt++) {
        int s = kt & 1;
        if (kt + 1 < NKC) prefetch(kt + 1, s ^ 1);
        if (kt + 1 < NKC) asm volatile("cp.async.wait_group 1;\n" ::: "memory");
        else              asm volatile("cp.async.wait_group 0;\n" ::: "memory");
        __syncthreads();

        // ---- S-tiles for this warp's 32-j half, exp2 with folded -log2(Z) ----
        uint32_t pa[2][4];
        const char* kB  = sm + AV_KOFF + s * AV_KSTAGE;
        const char* shB = sm + AV_SHOFF + s * AV_SHSTAGE;
#pragma unroll
        for (int tl = 0; tl < 4; tl++) {
            int tj = wj * 4 + tl;
            uint32_t bfrag = *(const uint32_t*)(kB + tj * 128 + kfoff);
            float2 shv = *(const float2*)(shB + tj * 32 + shloff);
            float c0 = 0.f, c1 = 0.f, c2 = 0.f, c3 = 0.f;
            mma1688(c0, c1, c2, c3, aq0, aq1, bfrag);
            pa[tl >> 1][(tl & 1) * 2 + 0] = hex2(pack_h2(c0 + shv.x, c1 + shv.y));
            pa[tl >> 1][(tl & 1) * 2 + 1] = hex2(pack_h2(c2 + shv.x, c3 + shv.y));
        }

        // ---- AV over this warp's 32-j half ----
        uint32_t vBase = sbase + s * AV_VSTAGE;
#pragma unroll
        for (int ks = 0; ks < 2; ks++) {
            uint32_t br[4][4];
            int ch = (wj * 2 + ks) * 2 + bchs;
#pragma unroll
            for (int nb = 0; nb < 4; nb++)
                ldsm4(br[nb][0], br[nb][1], br[nb][2], br[nb][3],
                      vBase + brow[nb] * 128 + ((ch ^ (brow[nb] & 7)) << 4));
#pragma unroll
            for (int ni = 0; ni < 8; ni++) {
                int nb = ni >> 1, sub = ni & 1;
                mma16816(d[ni][0], d[ni][1], d[ni][2], d[ni][3],
                         pa[ks][0], pa[ks][1], pa[ks][2], pa[ks][3],
                         br[nb][sub * 2], br[nb][sub * 2 + 1]);
            }
        }
        __syncthreads();
    }

    // ---- epilogue: merge wj halves in padded smem, transpose, residual ----
    float* sX = (float*)sm;                 // [64 c][132]
    int r = wm * 16 + (lane >> 2);
    if (wj == 0) {
#pragma unroll
        for (int ni = 0; ni < 8; ni++) {
            int c = ni * 8 + (lane & 3) * 2;
            sX[c * 132 + r]           = d[ni][0];
            sX[(c + 1) * 132 + r]     = d[ni][1];
            sX[c * 132 + r + 8]       = d[ni][2];
            sX[(c + 1) * 132 + r + 8] = d[ni][3];
        }
    }
    __syncthreads();
    if (wj == 1) {
#pragma unroll
        for (int ni = 0; ni < 8; ni++) {
            int c = ni * 8 + (lane & 3) * 2;
            sX[c * 132 + r]           += d[ni][0];
            sX[(c + 1) * 132 + r]     += d[ni][1];
            sX[c * 132 + r + 8]       += d[ni][2];
            sX[(c + 1) * 132 + r + 8] += d[ni][3];
        }
    }
    __syncthreads();

    const float* Yb = Y + (size_t)b * CIN * NTOK + i0;
    float* ob = out + (size_t)b * CIN * NTOK + i0;
#pragma unroll
    for (int t = 0; t < 4; t++) {
        int id = tid + t * 512;             // 2048 float4s
        int c = id >> 5, q4 = id & 31;
        const float* sp = sX + c * 132 + q4 * 4;
        float4 yv = *(const float4*)(Yb + (size_t)c * NTOK + q4 * 4);
        float4 o;
        o.x = yv.x + sp[0]; o.y = yv.y + sp[1]; o.z = yv.z + sp[2]; o.w = yv.w + sp[3];
        *(float4*)(ob + (size_t)c * NTOK + q4 * 4) = o;
    }
}

// ---------------- launch ----------------
extern "C" void kernel_launch(void* const* d_in, const int* in_sizes, int n_in,
                              void* d_out, int out_size) {
    const float* X  = (const float*)d_in[0];
    const float* Y  = (const float*)d_in[1];
    const float* Wq = (const float*)d_in[2];
    const float* bq = (const float*)d_in[3];
    const float* Wk = (const float*)d_in[4];
    const float* bk = (const float*)d_in[5];
    const float* Wv = (const float*)d_in[6];
    const float* bv = (const float*)d_in[7];
    float* out = (float*)d_out;

    cudaFuncSetAttribute(av2_kernel, cudaFuncAttributeMaxDynamicSharedMemorySize, AV_SMEM);

    qk_kernel<<<BATCH * NTOK / 128, 128>>>(X, Wq, bq, Wk, bk);
    zsum_kernel<<<BATCH * NT128, 256>>>();
    vscale_kernel<<<BATCH * NTOK / 128, 256>>>(Y, Wv, bv);
    av2_kernel<<<dim3(NT128, BATCH), 512, AV_SMEM>>>(Y, out);
}